// round 1
// baseline (speedup 1.0000x reference)
#include <cuda_runtime.h>
#include <math.h>

// ---------------- problem constants ----------------
constexpr int B_  = 4, C_ = 21, D_ = 300, H_ = 144, W_ = 144;
constexpr int HW_ = H_ * W_;              // 20736
constexpr int NT  = B_ * HW_;             // 82944  (multiple of 128)
constexpr int HO  = 142, WO = 142;
constexpr int HWO = HO * WO;              // 20164
constexpr int NH  = B_ * HWO;             // 80656
constexpr int NHP = 631 * 128;            // 80768 padded for GEMM
constexpr int KC  = 2700;                 // 300*9 im2col K
constexpr int KCP = 2704;
constexpr long long N300 = (long long)D_ * NT;  // 24,883,200

// ---------------- scratch (__device__ globals; allocation-free kernel_launch) --------
__device__ float g_E  [1800u * 82944u];   // 6 encoder outputs stacked: we1,we2,wfy1,wiy1,wfy2,wiy2
__device__ float g_G  [900u  * 82944u];   // stacked gate GEMM output: d,f,i
__device__ float g_c12[300u  * 82944u];
__device__ float g_x12[300u  * 82944u];
__device__ float g_xt1[300u  * 82944u];
__device__ float g_ct1[300u  * 82944u];
__device__ float g_Yx [21u   * 82944u];   // repacked input
__device__ float g_IM [2700u * 80768u];   // im2col (pad cols stay 0)
__device__ float g_H1 [128u  * 80768u];
__device__ float g_H2 [128u  * 80768u];
__device__ float g_Wenc[1800 * 24];
__device__ float g_benc[1800];
__device__ float g_W2p [900 * 304];
__device__ float g_b2p [900];
__device__ float g_W1p [900 * 304];
__device__ float g_b1p [900];
__device__ float g_Wl1 [128 * 2704];

// ---------------- device math ----------------
__device__ __forceinline__ float gelu_f(float x) {
    return 0.5f * x * (1.0f + erff(x * 0.70710678118654752440f));
}
__device__ __forceinline__ float sigm_f(float x) {
    return 1.0f / (1.0f + expf(-x));
}

// ---------------- pack kernels ----------------
__global__ void pack_enc(const float* __restrict__ w0, const float* __restrict__ w1,
                         const float* __restrict__ w2, const float* __restrict__ w3,
                         const float* __restrict__ w4, const float* __restrict__ w5,
                         const float* __restrict__ b0, const float* __restrict__ b1,
                         const float* __restrict__ b2, const float* __restrict__ b3,
                         const float* __restrict__ b4, const float* __restrict__ b5,
                         float* __restrict__ Wout, float* __restrict__ bout)
{
    const float* ws[6] = {w0, w1, w2, w3, w4, w5};
    const float* bs[6] = {b0, b1, b2, b3, b4, b5};
    int idx = blockIdx.x * blockDim.x + threadIdx.x;
    if (idx < 1800 * 24) {
        int m = idx / 24, k = idx % 24;
        int s = m / 300, r = m % 300;
        Wout[idx] = (k < 21) ? ws[s][r * 21 + k] : 0.0f;
    }
    if (idx < 1800) {
        int s = idx / 300, r = idx % 300;
        bout[idx] = bs[s][r];
    }
}

__global__ void pack_rec(const float* __restrict__ wd, const float* __restrict__ wf,
                         const float* __restrict__ wi,
                         const float* __restrict__ bd, const float* __restrict__ bf,
                         const float* __restrict__ bi,
                         float* __restrict__ Wout, float* __restrict__ bout)
{
    const float* ws[3] = {wd, wf, wi};
    const float* bs[3] = {bd, bf, bi};
    int idx = blockIdx.x * blockDim.x + threadIdx.x;
    if (idx < 900 * 304) {
        int m = idx / 304, k = idx % 304;
        int s = m / 300, r = m % 300;
        Wout[idx] = (k < 300) ? ws[s][r * 300 + k] : 0.0f;
    }
    if (idx < 900) {
        int s = idx / 300, r = idx % 300;
        bout[idx] = bs[s][r];
    }
}

__global__ void pack_line1(const float* __restrict__ w, float* __restrict__ Wout)
{
    int idx = blockIdx.x * blockDim.x + threadIdx.x;
    if (idx < 128 * KCP) {
        int oc = idx / KCP, k = idx % KCP;
        Wout[idx] = (k < KC) ? w[oc * KC + k] : 0.0f;
    }
}

__global__ void repack_y(const float* __restrict__ y, float* __restrict__ Yx)
{
    int idx = blockIdx.x * blockDim.x + threadIdx.x;
    if (idx < 21 * NT) {
        int k = idx / NT, n = idx % NT;
        int b = n / HW_, p = n % HW_;
        Yx[idx] = y[(b * 21 + k) * HW_ + p];
    }
}

// ---------------- GEMM: Y = gelu(W @ X + b), W[M][Kpad] padded, X[Kreal][N], N%128==0 -----
#define BM 128
#define BN 128
#define BK 8

__global__ void __launch_bounds__(256)
gemm_gelu(const float* __restrict__ W, const float* __restrict__ bias,
          const float* __restrict__ X, float* __restrict__ Y,
          int M, int Kpad, int Kreal, int N)
{
    __shared__ float Ws[BK][BM];
    __shared__ float Xs[BK][BN];

    int tid = threadIdx.x;
    int m0  = blockIdx.y * BM;
    long long n0 = (long long)blockIdx.x * BN;

    int xrow = tid >> 5, xcol = (tid & 31) << 2;   // X tile loader: 8 x 128
    int wrow = tid >> 1, wcol = (tid & 1) << 2;    // W tile loader: 128 x 8
    int tx = tid & 15, ty = tid >> 4;              // 16x16 compute grid

    const float* Xp = X + (long long)xrow * N + n0 + xcol;

    float acc[8][8];
#pragma unroll
    for (int i = 0; i < 8; i++)
#pragma unroll
        for (int j = 0; j < 8; j++) acc[i][j] = 0.0f;

    for (int k0 = 0; k0 < Kpad; k0 += BK) {
        float4 wv = make_float4(0.f, 0.f, 0.f, 0.f);
        int gm = m0 + wrow;
        if (gm < M) wv = *(const float4*)(W + (long long)gm * Kpad + k0 + wcol);
        float4 xv = make_float4(0.f, 0.f, 0.f, 0.f);
        int gk = k0 + xrow;
        if (gk < Kreal) xv = *(const float4*)(Xp + (long long)k0 * N);

        __syncthreads();
        Ws[wcol + 0][wrow] = wv.x;
        Ws[wcol + 1][wrow] = wv.y;
        Ws[wcol + 2][wrow] = wv.z;
        Ws[wcol + 3][wrow] = wv.w;
        *(float4*)&Xs[xrow][xcol] = xv;
        __syncthreads();

#pragma unroll
        for (int kk = 0; kk < BK; kk++) {
            float4 a0 = *(const float4*)&Ws[kk][ty * 4];
            float4 a1 = *(const float4*)&Ws[kk][64 + ty * 4];
            float4 b0 = *(const float4*)&Xs[kk][tx * 4];
            float4 b1 = *(const float4*)&Xs[kk][64 + tx * 4];
            float a[8] = {a0.x, a0.y, a0.z, a0.w, a1.x, a1.y, a1.z, a1.w};
            float b[8] = {b0.x, b0.y, b0.z, b0.w, b1.x, b1.y, b1.z, b1.w};
#pragma unroll
            for (int i = 0; i < 8; i++)
#pragma unroll
                for (int j = 0; j < 8; j++) acc[i][j] = fmaf(a[i], b[j], acc[i][j]);
        }
    }

#pragma unroll
    for (int i = 0; i < 8; i++) {
        int gm = m0 + ((i < 4) ? (ty * 4 + i) : (64 + ty * 4 + (i - 4)));
        if (gm < M) {
            float bb = bias[gm];
            float* yr = Y + (long long)gm * N + n0;
            float4 r0, r1;
            r0.x = gelu_f(acc[i][0] + bb); r0.y = gelu_f(acc[i][1] + bb);
            r0.z = gelu_f(acc[i][2] + bb); r0.w = gelu_f(acc[i][3] + bb);
            r1.x = gelu_f(acc[i][4] + bb); r1.y = gelu_f(acc[i][5] + bb);
            r1.z = gelu_f(acc[i][6] + bb); r1.w = gelu_f(acc[i][7] + bb);
            *(float4*)(yr + tx * 4)      = r0;
            *(float4*)(yr + 64 + tx * 4) = r1;
        }
    }
}

// ---------------- elementwise gate kernels ----------------
__global__ void init_ew(const float* __restrict__ E, float* __restrict__ c12,
                        float* __restrict__ x12, float* __restrict__ xt1)
{
    long long i = (long long)blockIdx.x * blockDim.x + threadIdx.x;
    if (i >= N300) return;
    float we1  = E[i];
    float wiy1 = E[i + 900LL * NT];
    float c = sigm_f(wiy1) * (-we1);
    c12[i] = c;
    x12[i] = fmaxf(c, 0.0f);
    xt1[i] = 0.0f;
}

// gates '2': ct1 = c12*sig(gf+ywfy2) + (ywe2 + xt1 - gd)*sig(gi+ywiy2); xt1 = relu(ct1)
__global__ void stepA_ew(const float* __restrict__ E, const float* __restrict__ G,
                         const float* __restrict__ c12, float* __restrict__ xt1,
                         float* __restrict__ ct1)
{
    long long i = (long long)blockIdx.x * blockDim.x + threadIdx.x;
    if (i >= N300) return;
    float gd = G[i], gf = G[i + N300], gi = G[i + 2 * N300];
    float f  = sigm_f(gf + E[i + 1200LL * NT]);
    float t  = sigm_f(gi + E[i + 1500LL * NT]);
    float ctl = E[i + 300LL * NT] + xt1[i] - gd;
    float c = c12[i] * f + ctl * t;
    ct1[i] = c;
    xt1[i] = fmaxf(c, 0.0f);
}

// gates '1': ct2 = ct1*sig(gf+ywfy1) + (ywe1 + xt1 - gd)*sig(gi+ywiy1); c12=ct2; x12=relu
__global__ void stepB_ew(const float* __restrict__ E, const float* __restrict__ G,
                         const float* __restrict__ ct1, const float* __restrict__ xt1,
                         float* __restrict__ c12, float* __restrict__ x12)
{
    long long i = (long long)blockIdx.x * blockDim.x + threadIdx.x;
    if (i >= N300) return;
    float gd = G[i], gf = G[i + N300], gi = G[i + 2 * N300];
    float f  = sigm_f(gf + E[i + 600LL * NT]);
    float t  = sigm_f(gi + E[i + 900LL * NT]);
    float ctl = E[i] + xt1[i] - gd;
    float c = ct1[i] * f + ctl * t;
    c12[i] = c;
    x12[i] = fmaxf(c, 0.0f);
}

// ---------------- im2col for 3x3 valid conv ----------------
__global__ void im2col_k(const float* __restrict__ xt1, float* __restrict__ IM)
{
    long long idx = (long long)blockIdx.x * blockDim.x + threadIdx.x;
    if (idx >= (long long)KC * NH) return;
    int k = (int)(idx / NH);
    int n = (int)(idx % NH);
    int c  = k / 9, r = k % 9, di = r / 3, dj = r % 3;
    int b  = n / HWO, q = n % HWO, i = q / WO, j = q % WO;
    IM[(long long)k * NHP + n] =
        xt1[(long long)c * NT + b * HW_ + (i + di) * W_ + (j + dj)];
}

// ---------------- final 128 -> 1 head ----------------
__global__ void head_out(const float* __restrict__ H2, const float* __restrict__ w3,
                         const float* __restrict__ b3, float* __restrict__ out)
{
    int n = blockIdx.x * blockDim.x + threadIdx.x;
    if (n >= NH) return;
    float s = b3[0];
#pragma unroll
    for (int c = 0; c < 128; c++) s = fmaf(w3[c], H2[(long long)c * NHP + n], s);
    out[n] = s;
}

// ---------------- launcher ----------------
extern "C" void kernel_launch(void* const* d_in, const int* in_sizes, int n_in,
                              void* d_out, int out_size)
{
    (void)in_sizes; (void)n_in; (void)out_size;
    const float* in[31];
    for (int i = 0; i < 31; i++) in[i] = (const float*)d_in[i];

    float *E, *G, *c12, *x12, *xt1, *ct1, *Yx, *IM, *H1, *H2;
    float *Wenc, *benc, *W2p, *b2p, *W1p, *b1p, *Wl1;
    cudaGetSymbolAddress((void**)&E,   g_E);
    cudaGetSymbolAddress((void**)&G,   g_G);
    cudaGetSymbolAddress((void**)&c12, g_c12);
    cudaGetSymbolAddress((void**)&x12, g_x12);
    cudaGetSymbolAddress((void**)&xt1, g_xt1);
    cudaGetSymbolAddress((void**)&ct1, g_ct1);
    cudaGetSymbolAddress((void**)&Yx,  g_Yx);
    cudaGetSymbolAddress((void**)&IM,  g_IM);
    cudaGetSymbolAddress((void**)&H1,  g_H1);
    cudaGetSymbolAddress((void**)&H2,  g_H2);
    cudaGetSymbolAddress((void**)&Wenc, g_Wenc);
    cudaGetSymbolAddress((void**)&benc, g_benc);
    cudaGetSymbolAddress((void**)&W2p,  g_W2p);
    cudaGetSymbolAddress((void**)&b2p,  g_b2p);
    cudaGetSymbolAddress((void**)&W1p,  g_W1p);
    cudaGetSymbolAddress((void**)&b1p,  g_b1p);
    cudaGetSymbolAddress((void**)&Wl1,  g_Wl1);

    // ---- pack weights / input ----
    pack_enc<<<(1800 * 24 + 255) / 256, 256>>>(
        in[1], in[3], in[5], in[7], in[9], in[11],
        in[2], in[4], in[6], in[8], in[10], in[12], Wenc, benc);
    pack_rec<<<(900 * 304 + 255) / 256, 256>>>(
        in[15], in[21], in[23], in[16], in[22], in[24], W2p, b2p);  // wd2, wfx2, wix2
    pack_rec<<<(900 * 304 + 255) / 256, 256>>>(
        in[13], in[17], in[19], in[14], in[18], in[20], W1p, b1p);  // wd1, wfx1, wix1
    pack_line1<<<(128 * KCP + 255) / 256, 256>>>(in[25], Wl1);
    repack_y<<<(21 * NT + 255) / 256, 256>>>(in[0], Yx);

    dim3 gN(NT / BN, 0, 1);
    int ewBlocks = (int)((N300 + 255) / 256);

    // ---- encoders: E = gelu(Wenc @ Yx + benc) ----
    gemm_gelu<<<dim3(NT / BN, 15), 256>>>(Wenc, benc, Yx, E, 1800, 24, 21, NT);

    // ---- init state ----
    init_ew<<<ewBlocks, 256>>>(E, c12, x12, xt1);

    // ---- 3 full iterations + final half-step ----
    for (int it = 0; it < 3; it++) {
        gemm_gelu<<<dim3(NT / BN, 8), 256>>>(W2p, b2p, x12, G, 900, 304, 300, NT);
        stepA_ew<<<ewBlocks, 256>>>(E, G, c12, xt1, ct1);
        gemm_gelu<<<dim3(NT / BN, 8), 256>>>(W1p, b1p, xt1, G, 900, 304, 300, NT);
        stepB_ew<<<ewBlocks, 256>>>(E, G, ct1, xt1, c12, x12);
    }
    gemm_gelu<<<dim3(NT / BN, 8), 256>>>(W2p, b2p, x12, G, 900, 304, 300, NT);
    stepA_ew<<<ewBlocks, 256>>>(E, G, c12, xt1, ct1);

    // ---- head ----
    long long imTot = (long long)KC * NH;
    im2col_k<<<(int)((imTot + 255) / 256), 256>>>(xt1, IM);
    gemm_gelu<<<dim3(NHP / BN, 1), 256>>>(Wl1, in[26], IM, H1, 128, KCP, KC, NHP);
    gemm_gelu<<<dim3(NHP / BN, 1), 256>>>(in[27], in[28], H1, H2, 128, 128, 128, NHP);
    head_out<<<(NH + 255) / 256, 256>>>(H2, in[29], in[30], (float*)d_out);
}